// round 11
// baseline (speedup 1.0000x reference)
#include <cuda_runtime.h>
#include <cstdint>

#define DI __device__ __forceinline__

// ---------------- tile config ----------------
static constexpr int BM = 128;    // token rows per CTA
static constexpr int BN = 256;    // output cols per CTA
static constexpr int BK = 64;     // K bytes per stage
static constexpr int STAGES = 4;
static constexpr int NTHREADS = 512;
static constexpr int ROWB = 80;   // smem row stride bytes (64 data + 16 pad, conflict-free)
static constexpr int STAGE_BYTES = (BM + BN) * ROWB;          // 30720
static constexpr int SMEM_TOTAL  = STAGES * STAGE_BYTES;      // 122880

// ---------------- scratch (device globals; no allocs allowed) ----------------
__device__ __align__(16) int8_t g_Wq[(size_t)4096 * 4096];
__device__ __align__(16) int8_t g_Xq[(size_t)8192 * 4096];
__device__ float  g_rs [4096];   // row scale of W
__device__ float  g_rsw[4096];   // rs[m] * sum_k Wq[m,k]
__device__ float  g_cs [8192];   // per-token scale of X
__device__ float  g_zp [8192];   // per-token zero point (integer-valued float)

// ---------------- PTX helpers ----------------
DI uint32_t smem_u32(const void* p) {
    uint32_t a;
    asm("{ .reg .u64 t; cvta.to.shared.u64 t, %1; cvt.u32.u64 %0, t; }" : "=r"(a) : "l"(p));
    return a;
}

DI void cp16(uint32_t smem_dst, const void* gptr) {
    asm volatile("cp.async.cg.shared.global [%0], [%1], 16;" :: "r"(smem_dst), "l"(gptr));
}

DI void ldmx4(uint32_t* r, uint32_t addr) {
    asm volatile("ldmatrix.sync.aligned.m8n8.x4.shared.b16 {%0,%1,%2,%3}, [%4];"
                 : "=r"(r[0]), "=r"(r[1]), "=r"(r[2]), "=r"(r[3]) : "r"(addr));
}

DI void mma_s8(int* d, const uint32_t* a, const uint32_t* b) {
    asm volatile(
        "mma.sync.aligned.m16n8k32.row.col.s32.s8.s8.s32 "
        "{%0,%1,%2,%3}, {%4,%5,%6,%7}, {%8,%9}, {%0,%1,%2,%3};"
        : "+r"(d[0]), "+r"(d[1]), "+r"(d[2]), "+r"(d[3])
        : "r"(a[0]), "r"(a[1]), "r"(a[2]), "r"(a[3]), "r"(b[0]), "r"(b[1]));
}

// ---------------- quantization kernels ----------------
// one block of 256 threads per row; K = 4096 (256 threads x 16 elems)

__global__ __launch_bounds__(256) void quant_w_kernel(const float* __restrict__ W, int K) {
    int m = blockIdx.x;
    int t = threadIdx.x;
    const float4* wrow = reinterpret_cast<const float4*>(W + (size_t)m * K);
    float v[16];
#pragma unroll
    for (int i = 0; i < 4; i++) {
        float4 f = wrow[t * 4 + i];
        v[i*4+0] = f.x; v[i*4+1] = f.y; v[i*4+2] = f.z; v[i*4+3] = f.w;
    }
    float amax = 0.f;
#pragma unroll
    for (int i = 0; i < 16; i++) amax = fmaxf(amax, fabsf(v[i]));
    __shared__ float rf[256];
    rf[t] = amax; __syncthreads();
    for (int s = 128; s > 0; s >>= 1) { if (t < s) rf[t] = fmaxf(rf[t], rf[t + s]); __syncthreads(); }
    float absmax = rf[0];
    float scale = absmax > 0.f ? absmax / 127.0f : 1.0f;

    union { int8_t b[16]; int4 v4; } u;
    int sum = 0;
#pragma unroll
    for (int i = 0; i < 16; i++) {
        float r = rintf(v[i] / scale);           // round-half-even == jnp.round
        r = fminf(127.f, fmaxf(-128.f, r));
        int qi = (int)r;
        sum += qi;
        u.b[i] = (int8_t)qi;
    }
    reinterpret_cast<int4*>(g_Wq + (size_t)m * K)[t] = u.v4;

    __shared__ int ri[256];
    ri[t] = sum; __syncthreads();
    for (int s = 128; s > 0; s >>= 1) { if (t < s) ri[t] += ri[t + s]; __syncthreads(); }
    if (t == 0) { g_rs[m] = scale; g_rsw[m] = scale * (float)ri[0]; }
}

__global__ __launch_bounds__(256) void quant_x_kernel(const float* __restrict__ X, int K) {
    int n = blockIdx.x;
    int t = threadIdx.x;
    const float4* xrow = reinterpret_cast<const float4*>(X + (size_t)n * K);
    float v[16];
#pragma unroll
    for (int i = 0; i < 4; i++) {
        float4 f = xrow[t * 4 + i];
        v[i*4+0] = f.x; v[i*4+1] = f.y; v[i*4+2] = f.z; v[i*4+3] = f.w;
    }
    float vmin = v[0], vmax = v[0];
#pragma unroll
    for (int i = 1; i < 16; i++) { vmin = fminf(vmin, v[i]); vmax = fmaxf(vmax, v[i]); }
    __shared__ float rmin[256], rmax[256];
    rmin[t] = vmin; rmax[t] = vmax; __syncthreads();
    for (int s = 128; s > 0; s >>= 1) {
        if (t < s) { rmin[t] = fminf(rmin[t], rmin[t + s]); rmax[t] = fmaxf(rmax[t], rmax[t + s]); }
        __syncthreads();
    }
    float lo = rmin[0], hi = rmax[0];
    float rng = hi - lo;
    float scale = rng > 0.f ? rng / 255.0f : 1.0f;   // QMAX-QMIN = 255
    float zp = rintf(-128.0f - lo / scale);
    zp = fminf(127.f, fmaxf(-128.f, zp));

    union { int8_t b[16]; int4 v4; } u;
#pragma unroll
    for (int i = 0; i < 16; i++) {
        float r = rintf(v[i] / scale + zp);
        r = fminf(127.f, fmaxf(-128.f, r));
        u.b[i] = (int8_t)(int)r;
    }
    reinterpret_cast<int4*>(g_Xq + (size_t)n * K)[t] = u.v4;
    if (t == 0) { g_cs[n] = scale; g_zp[n] = zp; }
}

// ---------------- int8 mma.sync GEMM + fused dequant epilogue ----------------
// CTA: 128x256x(K in 64B stages). 16 warps (2 m x 8 n); warp tile 64x32.
// A = Xq rows (tokens), B = Wq rows (output features). Both K-major int8.

DI void load_stage(uint32_t sbase, const int8_t* Ag, const int8_t* Bg,
                   int koff, int K, int tid) {
    uint32_t Ab = sbase;
    uint32_t Bb = sbase + BM * ROWB;
    // A: 128 rows x 4 chunks(16B) = 512 cp -> 1 per thread
    {
        int c = tid;                            // 0..511
        int r = c >> 2, off = (c & 3) * 16;
        cp16(Ab + r * ROWB + off, Ag + (size_t)r * K + koff + off);
    }
    // B: 256 rows x 4 chunks = 1024 cp -> 2 per thread
#pragma unroll
    for (int i = 0; i < 2; i++) {
        int c = tid + i * NTHREADS;             // 0..1023
        int r = c >> 2, off = (c & 3) * 16;
        cp16(Bb + r * ROWB + off, Bg + (size_t)r * K + koff + off);
    }
    asm volatile("cp.async.commit_group;" ::: "memory");
}

__global__ __launch_bounds__(NTHREADS, 1) void gemm_kernel(const float* __restrict__ bias,
                                                           float* __restrict__ out,
                                                           int Mout, int K) {
    extern __shared__ char smem[];
    uint32_t sb = smem_u32(smem);
    int tid = threadIdx.x, wid = tid >> 5, lid = tid & 31;
    int mwarp = wid >> 3;         // 0..1  (token dim, 64 rows each)
    int nwarp = wid & 7;          // 0..7  (output dim, 32 cols each)

    int tile_m0 = blockIdx.y * BM;   // token base
    int tile_n0 = blockIdx.x * BN;   // output feature base

    const int8_t* Ag = g_Xq + (size_t)tile_m0 * K;
    const int8_t* Bg = g_Wq + (size_t)tile_n0 * K;

    // per-lane ldmatrix address components (within a stage)
    // A: tile t = lid>>3 : row += (t&1)*8, col += (t>>1)*16
    int a_row = mwarp * 64 + ((lid >> 3) & 1) * 8 + (lid & 7);
    int a_col = ((lid >> 4) & 1) * 16;
    uint32_t a_off = (uint32_t)(a_row * ROWB + a_col);
    // B: tile t : row += (t>>1)*8, col += (t&1)*16
    int b_row = nwarp * 32 + ((lid >> 4) & 1) * 8 + (lid & 7);
    int b_col = ((lid >> 3) & 1) * 16;
    uint32_t b_off = (uint32_t)(BM * ROWB + b_row * ROWB + b_col);

    int acc[4][4][4];   // [mf][nf][reg]
#pragma unroll
    for (int i = 0; i < 4; i++)
#pragma unroll
        for (int j = 0; j < 4; j++)
#pragma unroll
            for (int r = 0; r < 4; r++) acc[i][j][r] = 0;

    const int KT = K / BK;   // 64
    // prologue: fill stages 0..2
    load_stage(sb + 0 * STAGE_BYTES, Ag, Bg, 0 * BK, K, tid);
    load_stage(sb + 1 * STAGE_BYTES, Ag, Bg, 1 * BK, K, tid);
    load_stage(sb + 2 * STAGE_BYTES, Ag, Bg, 2 * BK, K, tid);

    for (int s = 0; s < KT; s++) {
        asm volatile("cp.async.wait_group 2;" ::: "memory");
        __syncthreads();

        if (s + 3 < KT)
            load_stage(sb + ((s + 3) & (STAGES - 1)) * STAGE_BYTES, Ag, Bg, (s + 3) * BK, K, tid);
        else
            asm volatile("cp.async.commit_group;" ::: "memory");   // keep group count consistent

        uint32_t stage_base = sb + (s & (STAGES - 1)) * STAGE_BYTES;
#pragma unroll
        for (int ks = 0; ks < 2; ks++) {                 // two k32 steps per stage
            uint32_t afr[4][4];
#pragma unroll
            for (int mf = 0; mf < 4; mf++)
                ldmx4(afr[mf], stage_base + a_off + mf * (16 * ROWB) + ks * 32);
            uint32_t bfr[4][2];
#pragma unroll
            for (int p = 0; p < 2; p++) {
                uint32_t r[4];
                ldmx4(r, stage_base + b_off + p * (16 * ROWB) + ks * 32);
                bfr[2*p+0][0] = r[0]; bfr[2*p+0][1] = r[1];
                bfr[2*p+1][0] = r[2]; bfr[2*p+1][1] = r[3];
            }
#pragma unroll
            for (int mf = 0; mf < 4; mf++)
#pragma unroll
                for (int nf = 0; nf < 4; nf++)
                    mma_s8(acc[mf][nf], afr[mf], bfr[nf]);
        }
    }

    // ---------------- fused dequant epilogue ----------------
    // acc layout: rows (lane>>2) and +8; cols (lane&3)*2, +1
#pragma unroll
    for (int mf = 0; mf < 4; mf++) {
        int row0 = tile_m0 + mwarp * 64 + mf * 16 + (lid >> 2);
        int row1 = row0 + 8;
        float al0 = g_cs[row0], al1 = g_cs[row1];
        float be0 = -al0 * g_zp[row0], be1 = -al1 * g_zp[row1];
        float* o0 = out + (size_t)row0 * Mout;
        float* o1 = out + (size_t)row1 * Mout;
#pragma unroll
        for (int nf = 0; nf < 4; nf++) {
            int col = tile_n0 + nwarp * 32 + nf * 8 + (lid & 3) * 2;
            float2 rs2 = *reinterpret_cast<const float2*>(g_rs  + col);
            float2 rw2 = *reinterpret_cast<const float2*>(g_rsw + col);
            float2 bb2 = *reinterpret_cast<const float2*>(bias  + col);
            float2 y0, y1;
            y0.x = fmaf(al0 * (float)acc[mf][nf][0], rs2.x, fmaf(be0, rw2.x, bb2.x));
            y0.y = fmaf(al0 * (float)acc[mf][nf][1], rs2.y, fmaf(be0, rw2.y, bb2.y));
            y1.x = fmaf(al1 * (float)acc[mf][nf][2], rs2.x, fmaf(be1, rw2.x, bb2.x));
            y1.y = fmaf(al1 * (float)acc[mf][nf][3], rs2.y, fmaf(be1, rw2.y, bb2.y));
            *reinterpret_cast<float2*>(o0 + col) = y0;
            *reinterpret_cast<float2*>(o1 + col) = y1;
        }
    }
}

// ---------------- launch ----------------
extern "C" void kernel_launch(void* const* d_in, const int* in_sizes, int n_in,
                              void* d_out, int out_size) {
    const float* x = (const float*)d_in[0];
    const float* W = (const float*)d_in[1];
    const float* b = (const float*)d_in[2];
    float* out = (float*)d_out;

    int Mout = in_sizes[2];              // 4096 (bias length)
    int K    = in_sizes[1] / Mout;       // 4096
    int Ntok = in_sizes[0] / K;          // 8192

    quant_w_kernel<<<Mout, 256>>>(W, K);
    quant_x_kernel<<<Ntok, 256>>>(x, K);

    cudaFuncSetAttribute(gemm_kernel, cudaFuncAttributeMaxDynamicSharedMemorySize, SMEM_TOTAL);
    dim3 grid(Mout / BN, Ntok / BM);     // (16, 64)
    gemm_kernel<<<grid, NTHREADS, SMEM_TOTAL>>>(b, out, Mout, K);
}

// round 13
// speedup vs baseline: 2.1617x; 2.1617x over previous
#include <cuda_runtime.h>
#include <cuda_bf16.h>
#include <cstdint>

#define DI __device__ __forceinline__

// ---------------- tile config ----------------
static constexpr int BM = 128;    // token rows per CTA
static constexpr int BN = 256;    // output cols per CTA
static constexpr int BK = 64;     // K BYTES per stage (= 32 bf16 = 2 k16 mma steps)
static constexpr int STAGES = 4;
static constexpr int NTHREADS = 512;
static constexpr int ROWB = 80;   // smem row stride bytes (64 data + 16 pad, conflict-free)
static constexpr int STAGE_BYTES = (BM + BN) * ROWB;          // 30720
static constexpr int SMEM_TOTAL  = STAGES * STAGE_BYTES;      // 122880

// ---------------- scratch (device globals; no allocs allowed) ----------------
__device__ __align__(16) __nv_bfloat16 g_Wq[(size_t)4096 * 4096];   // quantized W (exact ints in bf16)
__device__ __align__(16) __nv_bfloat16 g_Xq[(size_t)8192 * 4096];   // quantized X
__device__ float  g_rs [4096];   // row scale of W
__device__ float  g_rsw[4096];   // rs[m] * sum_k Wq[m,k]
__device__ float  g_cs [8192];   // per-token scale of X
__device__ float  g_zp [8192];   // per-token zero point (integer-valued float)

// ---------------- PTX helpers ----------------
DI uint32_t smem_u32(const void* p) {
    uint32_t a;
    asm("{ .reg .u64 t; cvta.to.shared.u64 t, %1; cvt.u32.u64 %0, t; }" : "=r"(a) : "l"(p));
    return a;
}

DI void cp16(uint32_t smem_dst, const void* gptr) {
    asm volatile("cp.async.cg.shared.global [%0], [%1], 16;" :: "r"(smem_dst), "l"(gptr));
}

DI void ldmx4(uint32_t* r, uint32_t addr) {
    asm volatile("ldmatrix.sync.aligned.m8n8.x4.shared.b16 {%0,%1,%2,%3}, [%4];"
                 : "=r"(r[0]), "=r"(r[1]), "=r"(r[2]), "=r"(r[3]) : "r"(addr));
}

DI void mma_bf16(float* d, const uint32_t* a, const uint32_t* b) {
    asm volatile(
        "mma.sync.aligned.m16n8k16.row.col.f32.bf16.bf16.f32 "
        "{%0,%1,%2,%3}, {%4,%5,%6,%7}, {%8,%9}, {%0,%1,%2,%3};"
        : "+f"(d[0]), "+f"(d[1]), "+f"(d[2]), "+f"(d[3])
        : "r"(a[0]), "r"(a[1]), "r"(a[2]), "r"(a[3]), "r"(b[0]), "r"(b[1]));
}

// ---------------- fused quantization kernel ----------------
// Blocks [0, Mout): quantize W row m (symmetric per-row) -> g_Wq (bf16), g_rs, g_rsw
// Blocks [Mout, Mout+Ntok): quantize X row n (asymmetric per-token) -> g_Xq (bf16), g_cs, g_zp
// 256 threads/block; K = 4096 (256 x 16 elems). Quantized ints are exact in bf16.

__global__ __launch_bounds__(256) void quant_fused_kernel(const float* __restrict__ W,
                                                          const float* __restrict__ X,
                                                          int Mout, int K) {
    int t = threadIdx.x;
    __shared__ float rf0[256];
    __shared__ float rf1[256];
    __shared__ int   ri [256];

    if ((int)blockIdx.x < Mout) {
        int m = blockIdx.x;
        const float4* wrow = reinterpret_cast<const float4*>(W + (size_t)m * K);
        float v[16];
#pragma unroll
        for (int i = 0; i < 4; i++) {
            float4 f = wrow[t * 4 + i];
            v[i*4+0] = f.x; v[i*4+1] = f.y; v[i*4+2] = f.z; v[i*4+3] = f.w;
        }
        float amax = 0.f;
#pragma unroll
        for (int i = 0; i < 16; i++) amax = fmaxf(amax, fabsf(v[i]));
        rf0[t] = amax; __syncthreads();
        for (int s = 128; s > 0; s >>= 1) { if (t < s) rf0[t] = fmaxf(rf0[t], rf0[t + s]); __syncthreads(); }
        float absmax = rf0[0];
        float scale = absmax > 0.f ? absmax / 127.0f : 1.0f;

        union { __nv_bfloat16 h[16]; int4 v4[2]; } u;
        int sum = 0;
#pragma unroll
        for (int i = 0; i < 16; i++) {
            float r = rintf(v[i] / scale);           // round-half-even == jnp.round
            r = fminf(127.f, fmaxf(-128.f, r));
            int qi = (int)r;
            sum += qi;
            u.h[i] = __float2bfloat16(r);            // exact: |int| <= 128
        }
        int4* dst = reinterpret_cast<int4*>(g_Wq + (size_t)m * K);
        dst[t * 2 + 0] = u.v4[0];
        dst[t * 2 + 1] = u.v4[1];

        ri[t] = sum; __syncthreads();
        for (int s = 128; s > 0; s >>= 1) { if (t < s) ri[t] += ri[t + s]; __syncthreads(); }
        if (t == 0) { g_rs[m] = scale; g_rsw[m] = scale * (float)ri[0]; }
    } else {
        int n = blockIdx.x - Mout;
        const float4* xrow = reinterpret_cast<const float4*>(X + (size_t)n * K);
        float v[16];
#pragma unroll
        for (int i = 0; i < 4; i++) {
            float4 f = xrow[t * 4 + i];
            v[i*4+0] = f.x; v[i*4+1] = f.y; v[i*4+2] = f.z; v[i*4+3] = f.w;
        }
        float vmin = v[0], vmax = v[0];
#pragma unroll
        for (int i = 1; i < 16; i++) { vmin = fminf(vmin, v[i]); vmax = fmaxf(vmax, v[i]); }
        rf0[t] = vmin; rf1[t] = vmax; __syncthreads();
        for (int s = 128; s > 0; s >>= 1) {
            if (t < s) { rf0[t] = fminf(rf0[t], rf0[t + s]); rf1[t] = fmaxf(rf1[t], rf1[t + s]); }
            __syncthreads();
        }
        float lo = rf0[0], hi = rf1[0];
        float rng = hi - lo;
        float scale = rng > 0.f ? rng / 255.0f : 1.0f;   // QMAX-QMIN = 255
        float zp = rintf(-128.0f - lo / scale);
        zp = fminf(127.f, fmaxf(-128.f, zp));

        union { __nv_bfloat16 h[16]; int4 v4[2]; } u;
#pragma unroll
        for (int i = 0; i < 16; i++) {
            float r = rintf(v[i] / scale + zp);
            r = fminf(127.f, fmaxf(-128.f, r));
            u.h[i] = __float2bfloat16(r);            // exact int
        }
        int4* dst = reinterpret_cast<int4*>(g_Xq + (size_t)n * K);
        dst[t * 2 + 0] = u.v4[0];
        dst[t * 2 + 1] = u.v4[1];
        if (t == 0) { g_cs[n] = scale; g_zp[n] = zp; }
    }
}

// ---------------- bf16 HMMA GEMM + fused dequant epilogue ----------------
// CTA: 128x256, K in 64-BYTE stages (32 bf16). 16 warps (2 m x 8 n); warp tile 64x32.
// A = Xq rows (tokens), B = Wq rows (output features). Both K-major bf16 holding exact ints.
// Byte-layout of fragments identical to the (emulated) s8 path that passed in R10;
// bf16 m16n8k16 runs on the real HMMA tensor pipe.

__global__ __launch_bounds__(NTHREADS, 1) void gemm_kernel(const float* __restrict__ bias,
                                                           float* __restrict__ out,
                                                           int Mout, int K) {
    extern __shared__ char smem[];
    uint32_t sb = smem_u32(smem);
    int tid = threadIdx.x, wid = tid >> 5, lid = tid & 31;
    int mwarp = wid >> 3;         // 0..1  (token dim, 64 rows each)
    int nwarp = wid & 7;          // 0..7  (output dim, 32 cols each)

    int tile_m0 = blockIdx.y * BM;   // token base
    int tile_n0 = blockIdx.x * BN;   // output feature base

    const int KB = K * 2;            // bytes per row (bf16)

    // per-thread loader addresses (running byte pointers; += BK per stage)
    int lrow = tid >> 2;                       // 0..127
    int loff = (tid & 3) * 16;                 // 0/16/32/48 bytes
    const int8_t* gA  = reinterpret_cast<const int8_t*>(g_Xq) + (size_t)(tile_m0 + lrow) * KB + loff;
    const int8_t* gB0 = reinterpret_cast<const int8_t*>(g_Wq) + (size_t)(tile_n0 + lrow) * KB + loff;
    const int8_t* gB1 = reinterpret_cast<const int8_t*>(g_Wq) + (size_t)(tile_n0 + 128 + lrow) * KB + loff;
    uint32_t sA  = (uint32_t)(lrow * ROWB + loff);
    uint32_t sB0 = (uint32_t)(BM * ROWB + lrow * ROWB + loff);
    uint32_t sB1 = sB0 + 128u * ROWB;

    // per-lane ldmatrix address components (within a stage); byte-identical to s8 path
    int a_row = mwarp * 64 + ((lid >> 3) & 1) * 8 + (lid & 7);
    int a_col = ((lid >> 4) & 1) * 16;
    uint32_t a_off = (uint32_t)(a_row * ROWB + a_col);
    int b_row = nwarp * 32 + ((lid >> 4) & 1) * 8 + (lid & 7);
    int b_col = ((lid >> 3) & 1) * 16;
    uint32_t b_off = (uint32_t)(BM * ROWB + b_row * ROWB + b_col);

    float acc[4][4][4];   // [mf][nf][reg]
#pragma unroll
    for (int i = 0; i < 4; i++)
#pragma unroll
        for (int j = 0; j < 4; j++)
#pragma unroll
            for (int r = 0; r < 4; r++) acc[i][j][r] = 0.f;

    const int KT = KB / BK;   // 128 stages
    // prologue: fill stages 0..2
#pragma unroll
    for (int p = 0; p < 3; p++) {
        uint32_t sbase = sb + p * STAGE_BYTES;
        cp16(sbase + sA,  gA);
        cp16(sbase + sB0, gB0);
        cp16(sbase + sB1, gB1);
        asm volatile("cp.async.commit_group;" ::: "memory");
        gA += BK; gB0 += BK; gB1 += BK;
    }

    for (int s = 0; s < KT; s++) {
        asm volatile("cp.async.wait_group 2;" ::: "memory");
        __syncthreads();

        if (s + 3 < KT) {
            uint32_t sbase = sb + ((s + 3) & (STAGES - 1)) * STAGE_BYTES;
            cp16(sbase + sA,  gA);
            cp16(sbase + sB0, gB0);
            cp16(sbase + sB1, gB1);
            asm volatile("cp.async.commit_group;" ::: "memory");
            gA += BK; gB0 += BK; gB1 += BK;
        } else {
            asm volatile("cp.async.commit_group;" ::: "memory");   // keep group count consistent
        }

        uint32_t stage_base = sb + (s & (STAGES - 1)) * STAGE_BYTES;
#pragma unroll
        for (int ks = 0; ks < 2; ks++) {                 // two k16 steps per 64B stage
            uint32_t afr[4][4];
#pragma unroll
            for (int mf = 0; mf < 4; mf++)
                ldmx4(afr[mf], stage_base + a_off + mf * (16 * ROWB) + ks * 32);
            uint32_t bfr[4][2];
#pragma unroll
            for (int p = 0; p < 2; p++) {
                uint32_t r[4];
                ldmx4(r, stage_base + b_off + p * (16 * ROWB) + ks * 32);
                bfr[2*p+0][0] = r[0]; bfr[2*p+0][1] = r[1];
                bfr[2*p+1][0] = r[2]; bfr[2*p+1][1] = r[3];
            }
#pragma unroll
            for (int mf = 0; mf < 4; mf++)
#pragma unroll
                for (int nf = 0; nf < 4; nf++)
                    mma_bf16(acc[mf][nf], afr[mf], bfr[nf]);
        }
    }

    // ---------------- fused dequant epilogue ----------------
    // acc layout: rows (lane>>2) and +8; cols (lane&3)*2, +1
#pragma unroll
    for (int mf = 0; mf < 4; mf++) {
        int row0 = tile_m0 + mwarp * 64 + mf * 16 + (lid >> 2);
        int row1 = row0 + 8;
        float al0 = g_cs[row0], al1 = g_cs[row1];
        float be0 = -al0 * g_zp[row0], be1 = -al1 * g_zp[row1];
        float* o0 = out + (size_t)row0 * Mout;
        float* o1 = out + (size_t)row1 * Mout;
#pragma unroll
        for (int nf = 0; nf < 4; nf++) {
            int col = tile_n0 + nwarp * 32 + nf * 8 + (lid & 3) * 2;
            float2 rs2 = *reinterpret_cast<const float2*>(g_rs  + col);
            float2 rw2 = *reinterpret_cast<const float2*>(g_rsw + col);
            float2 bb2 = *reinterpret_cast<const float2*>(bias  + col);
            float2 y0, y1;
            y0.x = fmaf(al0 * acc[mf][nf][0], rs2.x, fmaf(be0, rw2.x, bb2.x));
            y0.y = fmaf(al0 * acc[mf][nf][1], rs2.y, fmaf(be0, rw2.y, bb2.y));
            y1.x = fmaf(al1 * acc[mf][nf][2], rs2.x, fmaf(be1, rw2.x, bb2.x));
            y1.y = fmaf(al1 * acc[mf][nf][3], rs2.y, fmaf(be1, rw2.y, bb2.y));
            *reinterpret_cast<float2*>(o0 + col) = y0;
            *reinterpret_cast<float2*>(o1 + col) = y1;
        }
    }
}

// ---------------- launch ----------------
extern "C" void kernel_launch(void* const* d_in, const int* in_sizes, int n_in,
                              void* d_out, int out_size) {
    const float* x = (const float*)d_in[0];
    const float* W = (const float*)d_in[1];
    const float* b = (const float*)d_in[2];
    float* out = (float*)d_out;

    int Mout = in_sizes[2];              // 4096 (bias length)
    int K    = in_sizes[1] / Mout;       // 4096
    int Ntok = in_sizes[0] / K;          // 8192

    quant_fused_kernel<<<Mout + Ntok, 256>>>(W, x, Mout, K);

    cudaFuncSetAttribute(gemm_kernel, cudaFuncAttributeMaxDynamicSharedMemorySize, SMEM_TOTAL);
    dim3 grid(Mout / BN, Ntok / BM);     // (16, 64)
    gemm_kernel<<<grid, NTHREADS, SMEM_TOTAL>>>(b, out, Mout, K);
}

// round 16
// speedup vs baseline: 2.4340x; 1.1260x over previous
#include <cuda_runtime.h>
#include <cuda_bf16.h>
#include <cstdint>

#define DI __device__ __forceinline__

// ---------------- tile config ----------------
static constexpr int BM = 128;    // token rows per CTA
static constexpr int BN = 256;    // output cols per CTA
static constexpr int BK = 128;    // K BYTES per stage (= 64 bf16 = 4 k16 mma steps)
static constexpr int STAGES = 4;
static constexpr int NTHREADS = 512;
static constexpr int ROWB = 144;  // smem row stride bytes (128 data + 16 pad, conflict-free)
static constexpr int STAGE_BYTES = (BM + BN) * ROWB;          // 55296
static constexpr int SMEM_TOTAL  = STAGES * STAGE_BYTES;      // 221184

// ---------------- scratch (device globals; no allocs allowed) ----------------
__device__ __align__(16) __nv_bfloat16 g_Wq[(size_t)4096 * 4096];   // quantized W (exact ints in bf16)
__device__ __align__(16) __nv_bfloat16 g_Xq[(size_t)8192 * 4096];   // quantized X
__device__ float  g_rs [4096];   // row scale of W
__device__ float  g_rsw[4096];   // rs[m] * sum_k Wq[m,k]
__device__ float  g_cs [8192];   // per-token scale of X
__device__ float  g_zp [8192];   // per-token zero point (integer-valued float)

// ---------------- PTX helpers ----------------
DI uint32_t smem_u32(const void* p) {
    uint32_t a;
    asm("{ .reg .u64 t; cvta.to.shared.u64 t, %1; cvt.u32.u64 %0, t; }" : "=r"(a) : "l"(p));
    return a;
}

DI void cp16(uint32_t smem_dst, const void* gptr) {
    asm volatile("cp.async.cg.shared.global [%0], [%1], 16;" :: "r"(smem_dst), "l"(gptr));
}

DI void ldmx4(uint32_t* r, uint32_t addr) {
    asm volatile("ldmatrix.sync.aligned.m8n8.x4.shared.b16 {%0,%1,%2,%3}, [%4];"
                 : "=r"(r[0]), "=r"(r[1]), "=r"(r[2]), "=r"(r[3]) : "r"(addr));
}

DI void mma_bf16(float* d, const uint32_t* a, const uint32_t* b) {
    asm volatile(
        "mma.sync.aligned.m16n8k16.row.col.f32.bf16.bf16.f32 "
        "{%0,%1,%2,%3}, {%4,%5,%6,%7}, {%8,%9}, {%0,%1,%2,%3};"
        : "+f"(d[0]), "+f"(d[1]), "+f"(d[2]), "+f"(d[3])
        : "r"(a[0]), "r"(a[1]), "r"(a[2]), "r"(a[3]), "r"(b[0]), "r"(b[1]));
}

// ---------------- fused quantization kernel ----------------
// Blocks [0, Mout): quantize W row m (symmetric per-row) -> g_Wq (bf16), g_rs, g_rsw
// Blocks [Mout, Mout+Ntok): quantize X row n (asymmetric per-token) -> g_Xq (bf16), g_cs, g_zp

__global__ __launch_bounds__(256) void quant_fused_kernel(const float* __restrict__ W,
                                                          const float* __restrict__ X,
                                                          int Mout, int K) {
    int t = threadIdx.x;
    __shared__ float rf0[256];
    __shared__ float rf1[256];
    __shared__ int   ri [256];

    if ((int)blockIdx.x < Mout) {
        int m = blockIdx.x;
        const float4* wrow = reinterpret_cast<const float4*>(W + (size_t)m * K);
        float v[16];
#pragma unroll
        for (int i = 0; i < 4; i++) {
            float4 f = wrow[t * 4 + i];
            v[i*4+0] = f.x; v[i*4+1] = f.y; v[i*4+2] = f.z; v[i*4+3] = f.w;
        }
        float amax = 0.f;
#pragma unroll
        for (int i = 0; i < 16; i++) amax = fmaxf(amax, fabsf(v[i]));
        rf0[t] = amax; __syncthreads();
        for (int s = 128; s > 0; s >>= 1) { if (t < s) rf0[t] = fmaxf(rf0[t], rf0[t + s]); __syncthreads(); }
        float absmax = rf0[0];
        float scale = absmax > 0.f ? absmax / 127.0f : 1.0f;

        union { __nv_bfloat16 h[16]; int4 v4[2]; } u;
        int sum = 0;
#pragma unroll
        for (int i = 0; i < 16; i++) {
            float r = rintf(v[i] / scale);           // round-half-even == jnp.round
            r = fminf(127.f, fmaxf(-128.f, r));
            int qi = (int)r;
            sum += qi;
            u.h[i] = __float2bfloat16(r);            // exact: |int| <= 128
        }
        int4* dst = reinterpret_cast<int4*>(g_Wq + (size_t)m * K);
        dst[t * 2 + 0] = u.v4[0];
        dst[t * 2 + 1] = u.v4[1];

        ri[t] = sum; __syncthreads();
        for (int s = 128; s > 0; s >>= 1) { if (t < s) ri[t] += ri[t + s]; __syncthreads(); }
        if (t == 0) { g_rs[m] = scale; g_rsw[m] = scale * (float)ri[0]; }
    } else {
        int n = blockIdx.x - Mout;
        const float4* xrow = reinterpret_cast<const float4*>(X + (size_t)n * K);
        float v[16];
#pragma unroll
        for (int i = 0; i < 4; i++) {
            float4 f = xrow[t * 4 + i];
            v[i*4+0] = f.x; v[i*4+1] = f.y; v[i*4+2] = f.z; v[i*4+3] = f.w;
        }
        float vmin = v[0], vmax = v[0];
#pragma unroll
        for (int i = 1; i < 16; i++) { vmin = fminf(vmin, v[i]); vmax = fmaxf(vmax, v[i]); }
        rf0[t] = vmin; rf1[t] = vmax; __syncthreads();
        for (int s = 128; s > 0; s >>= 1) {
            if (t < s) { rf0[t] = fminf(rf0[t], rf0[t + s]); rf1[t] = fmaxf(rf1[t], rf1[t + s]); }
            __syncthreads();
        }
        float lo = rf0[0], hi = rf1[0];
        float rng = hi - lo;
        float scale = rng > 0.f ? rng / 255.0f : 1.0f;   // QMAX-QMIN = 255
        float zp = rintf(-128.0f - lo / scale);
        zp = fminf(127.f, fmaxf(-128.f, zp));

        union { __nv_bfloat16 h[16]; int4 v4[2]; } u;
#pragma unroll
        for (int i = 0; i < 16; i++) {
            float r = rintf(v[i] / scale + zp);
            r = fminf(127.f, fmaxf(-128.f, r));
            u.h[i] = __float2bfloat16(r);            // exact int
        }
        int4* dst = reinterpret_cast<int4*>(g_Xq + (size_t)n * K);
        dst[t * 2 + 0] = u.v4[0];
        dst[t * 2 + 1] = u.v4[1];
        if (t == 0) { g_cs[n] = scale; g_zp[n] = zp; }
    }
}

// ---------------- bf16 HMMA GEMM + fused dequant epilogue ----------------
// CTA: 128x256, K in 128-BYTE stages (64 bf16 = 4 k16 steps). 16 warps (2m x 8n);
// warp tile 64x32. A = Xq (tokens), B = Wq (features), K-major bf16 exact ints.

__global__ __launch_bounds__(NTHREADS, 1) void gemm_kernel(const float* __restrict__ bias,
                                                           float* __restrict__ out,
                                                           int Mout, int K) {
    extern __shared__ char smem[];
    uint32_t sb = smem_u32(smem);
    int tid = threadIdx.x, wid = tid >> 5, lid = tid & 31;
    int mwarp = wid >> 3;         // 0..1  (token dim, 64 rows each)
    int nwarp = wid & 7;          // 0..7  (output dim, 32 cols each)

    int tile_m0 = blockIdx.y * BM;   // token base
    int tile_n0 = blockIdx.x * BN;   // output feature base

    const int KB = K * 2;            // bytes per row (bf16)

    // loader: 512 threads cover 64 rows x 8 16B-chunks per pass; A 2 passes, B 4 passes
    int lrow8 = tid >> 3;                      // 0..63
    int loff8 = (tid & 7) * 16;                // 0..112 bytes
    const int8_t* gA0 = reinterpret_cast<const int8_t*>(g_Xq) + (size_t)(tile_m0 + lrow8) * KB + loff8;
    const int8_t* gA1 = gA0 + (size_t)64 * KB;
    const int8_t* gB0 = reinterpret_cast<const int8_t*>(g_Wq) + (size_t)(tile_n0 + lrow8) * KB + loff8;
    const int8_t* gB1 = gB0 + (size_t)64 * KB;
    const int8_t* gB2 = gB0 + (size_t)128 * KB;
    const int8_t* gB3 = gB0 + (size_t)192 * KB;
    uint32_t sA0 = (uint32_t)(lrow8 * ROWB + loff8);
    uint32_t sA1 = sA0 + 64u * ROWB;
    uint32_t sB0 = (uint32_t)(BM * ROWB) + sA0;
    uint32_t sB1 = sB0 + 64u * ROWB;
    uint32_t sB2 = sB0 + 128u * ROWB;
    uint32_t sB3 = sB0 + 192u * ROWB;

    // per-lane ldmatrix address components (within a stage)
    int a_row = mwarp * 64 + ((lid >> 3) & 1) * 8 + (lid & 7);
    int a_col = ((lid >> 4) & 1) * 16;
    uint32_t a_off = (uint32_t)(a_row * ROWB + a_col);
    int b_row = nwarp * 32 + ((lid >> 4) & 1) * 8 + (lid & 7);
    int b_col = ((lid >> 3) & 1) * 16;
    uint32_t b_off = (uint32_t)(BM * ROWB + b_row * ROWB + b_col);

    float acc[4][4][4];   // [mf][nf][reg]
#pragma unroll
    for (int i = 0; i < 4; i++)
#pragma unroll
        for (int j = 0; j < 4; j++)
#pragma unroll
            for (int r = 0; r < 4; r++) acc[i][j][r] = 0.f;

    const int KT = KB / BK;   // 64 stages
    // prologue: fill stages 0..2
#pragma unroll
    for (int p = 0; p < 3; p++) {
        uint32_t sbase = sb + p * STAGE_BYTES;
        cp16(sbase + sA0, gA0);  cp16(sbase + sA1, gA1);
        cp16(sbase + sB0, gB0);  cp16(sbase + sB1, gB1);
        cp16(sbase + sB2, gB2);  cp16(sbase + sB3, gB3);
        asm volatile("cp.async.commit_group;" ::: "memory");
        gA0 += BK; gA1 += BK; gB0 += BK; gB1 += BK; gB2 += BK; gB3 += BK;
    }

    for (int s = 0; s < KT; s++) {
        asm volatile("cp.async.wait_group 2;" ::: "memory");
        __syncthreads();

        if (s + 3 < KT) {
            uint32_t sbase = sb + ((s + 3) & (STAGES - 1)) * STAGE_BYTES;
            cp16(sbase + sA0, gA0);  cp16(sbase + sA1, gA1);
            cp16(sbase + sB0, gB0);  cp16(sbase + sB1, gB1);
            cp16(sbase + sB2, gB2);  cp16(sbase + sB3, gB3);
            asm volatile("cp.async.commit_group;" ::: "memory");
            gA0 += BK; gA1 += BK; gB0 += BK; gB1 += BK; gB2 += BK; gB3 += BK;
        } else {
            asm volatile("cp.async.commit_group;" ::: "memory");   // keep group count consistent
        }

        uint32_t stage_base = sb + (s & (STAGES - 1)) * STAGE_BYTES;
#pragma unroll
        for (int ks = 0; ks < 4; ks++) {                 // four k16 steps per 128B stage
            uint32_t afr[4][4];
#pragma unroll
            for (int mf = 0; mf < 4; mf++)
                ldmx4(afr[mf], stage_base + a_off + mf * (16 * ROWB) + ks * 32);
            uint32_t bfr[4][2];
#pragma unroll
            for (int p = 0; p < 2; p++) {
                uint32_t r[4];
                ldmx4(r, stage_base + b_off + p * (16 * ROWB) + ks * 32);
                bfr[2*p+0][0] = r[0]; bfr[2*p+0][1] = r[1];
                bfr[2*p+1][0] = r[2]; bfr[2*p+1][1] = r[3];
            }
#pragma unroll
            for (int mf = 0; mf < 4; mf++)
#pragma unroll
                for (int nf = 0; nf < 4; nf++)
                    mma_bf16(acc[mf][nf], afr[mf], bfr[nf]);
        }
    }

    // ---------------- fused dequant epilogue ----------------
#pragma unroll
    for (int mf = 0; mf < 4; mf++) {
        int row0 = tile_m0 + mwarp * 64 + mf * 16 + (lid >> 2);
        int row1 = row0 + 8;
        float al0 = g_cs[row0], al1 = g_cs[row1];
        float be0 = -al0 * g_zp[row0], be1 = -al1 * g_zp[row1];
        float* o0 = out + (size_t)row0 * Mout;
        float* o1 = out + (size_t)row1 * Mout;
#pragma unroll
        for (int nf = 0; nf < 4; nf++) {
            int col = tile_n0 + nwarp * 32 + nf * 8 + (lid & 3) * 2;
            float2 rs2 = *reinterpret_cast<const float2*>(g_rs  + col);
            float2 rw2 = *reinterpret_cast<const float2*>(g_rsw + col);
            float2 bb2 = *reinterpret_cast<const float2*>(bias  + col);
            float2 y0, y1;
            y0.x = fmaf(al0 * acc[mf][nf][0], rs2.x, fmaf(be0, rw2.x, bb2.x));
            y0.y = fmaf(al0 * acc[mf][nf][1], rs2.y, fmaf(be0, rw2.y, bb2.y));
            y1.x = fmaf(al1 * acc[mf][nf][2], rs2.x, fmaf(be1, rw2.x, bb2.x));
            y1.y = fmaf(al1 * acc[mf][nf][3], rs2.y, fmaf(be1, rw2.y, bb2.y));
            *reinterpret_cast<float2*>(o0 + col) = y0;
            *reinterpret_cast<float2*>(o1 + col) = y1;
        }
    }
}

// ---------------- launch ----------------
extern "C" void kernel_launch(void* const* d_in, const int* in_sizes, int n_in,
                              void* d_out, int out_size) {
    const float* x = (const float*)d_in[0];
    const float* W = (const float*)d_in[1];
    const float* b = (const float*)d_in[2];
    float* out = (float*)d_out;

    int Mout = in_sizes[2];              // 4096 (bias length)
    int K    = in_sizes[1] / Mout;       // 4096
    int Ntok = in_sizes[0] / K;          // 8192

    quant_fused_kernel<<<Mout + Ntok, 256>>>(W, x, Mout, K);

    cudaFuncSetAttribute(gemm_kernel, cudaFuncAttributeMaxDynamicSharedMemorySize, SMEM_TOTAL);
    dim3 grid(Mout / BN, Ntok / BM);     // (16, 64)
    gemm_kernel<<<grid, NTHREADS, SMEM_TOTAL>>>(b, out, Mout, K);
}